// round 1
// baseline (speedup 1.0000x reference)
#include <cuda_runtime.h>
#include <cstdint>

#define THREADS 512
#define ELEMS   16384
#define VEC_ITER (ELEMS / 4 / THREADS)   // 8 float4 loads per thread
#define KSEL    32

// Order-preserving float -> uint32 key (ascending float <-> ascending unsigned)
__device__ __forceinline__ unsigned f2key(float f) {
    unsigned u = __float_as_uint(f);
    return (u & 0x80000000u) ? ~u : (u | 0x80000000u);
}
// relu(value) recovered from key: keys with MSB=0 are negative floats -> 0
__device__ __forceinline__ float key2relu(unsigned k) {
    return (k & 0x80000000u) ? __uint_as_float(k ^ 0x80000000u) : 0.0f;
}

__global__ __launch_bounds__(THREADS)
void splittopk_kernel(const float* __restrict__ x, float* __restrict__ out)
{
    extern __shared__ unsigned keys[];   // 16384 keys = 64 KB dynamic smem
    __shared__ unsigned hist[256];
    __shared__ unsigned s_prefix;
    __shared__ int s_k;
    __shared__ int s_eqcnt;
    __shared__ int eq_idx[64];

    const int tid = threadIdx.x;
    const long long base = (long long)blockIdx.x * ELEMS;
    const float4* __restrict__ x4 = (const float4*)(x + base);
    float4* __restrict__ o4 = (float4*)(out + base);

    // ---- Load tile -> keys in smem; zero the output tile in the same sweep ----
    #pragma unroll
    for (int j = 0; j < VEC_ITER; ++j) {
        int p = j * THREADS + tid;
        float4 v = x4[p];
        uint4 kk;
        kk.x = f2key(v.x); kk.y = f2key(v.y);
        kk.z = f2key(v.z); kk.w = f2key(v.w);
        ((uint4*)keys)[p] = kk;
        o4[p] = make_float4(0.f, 0.f, 0.f, 0.f);
    }
    if (tid == 0) { s_prefix = 0u; s_k = KSEL; s_eqcnt = 0; }
    __syncthreads();

    // ---- Exact descending radix-select, 4 x 8-bit passes over smem keys ----
    #pragma unroll
    for (int pass = 0; pass < 4; ++pass) {
        const int shift = 24 - pass * 8;
        if (tid < 256) hist[tid] = 0u;
        __syncthreads();
        const unsigned pmask = (pass == 0) ? 0u : (0xFFFFFFFFu << (shift + 8));
        const unsigned pfx = s_prefix;       // bits above 'shift' decided so far
        for (int i = tid; i < ELEMS; i += THREADS) {
            unsigned k = keys[i];
            bool pred = ((k & pmask) == pfx);
            unsigned bal = __ballot_sync(0xFFFFFFFFu, pred);
            if (pred) {
                unsigned bin = (k >> shift) & 0xFFu;
                unsigned peers = __match_any_sync(bal, bin);
                if ((__ffs(peers) - 1) == (tid & 31))
                    atomicAdd(&hist[bin], __popc(peers));
            }
        }
        __syncthreads();
        if (tid == 0) {
            int cnt = 0;
            int b = 255;
            for (; b > 0; --b) {
                int h = (int)hist[b];
                if (cnt + h >= s_k) break;
                cnt += h;
            }
            s_prefix = pfx | ((unsigned)b << shift);
            s_k -= cnt;
        }
        __syncthreads();
    }

    const unsigned T = s_prefix;   // key of the 32nd-largest element
    const int kneed  = s_k;        // how many ==T elements to keep
    const float vT   = key2relu(T);

    // ---- Winner pass: strict winners write directly; equals are gathered ----
    for (int i = tid; i < ELEMS; i += THREADS) {
        unsigned k = keys[i];
        if (k > T) {
            out[base + i] = key2relu(k);
        } else if (k == T) {
            int p = atomicAdd(&s_eqcnt, 1);
            if (p < 64) eq_idx[p] = i;
        }
    }
    __syncthreads();

    const int eqc = s_eqcnt;       // total count of ==T (always >= kneed)
    if (eqc == kneed) {
        // No real ties at the threshold (overwhelmingly common case).
        if (tid < eqc) out[base + eq_idx[tid]] = vT;
    } else {
        // fp32 tie at the threshold: keep the kneed smallest indices
        // (matches jax top_k stable tie-breaking). Rare cold path.
        for (int i = tid; i < ELEMS; i += THREADS) {
            if (keys[i] == T) {
                int rank = 0;
                for (int j = 0; j < i; ++j) rank += (keys[j] == T);
                if (rank < kneed) out[base + i] = vT;
            }
        }
    }
}

extern "C" void kernel_launch(void* const* d_in, const int* in_sizes, int n_in,
                              void* d_out, int out_size) {
    const float* x = (const float*)d_in[0];
    float* out = (float*)d_out;

    // 64 KB dynamic smem needs the opt-in attribute (idempotent; not a stream op,
    // legal during graph capture; no allocation).
    cudaFuncSetAttribute(splittopk_kernel,
                         cudaFuncAttributeMaxDynamicSharedMemorySize, 65536);

    int nblocks = out_size / ELEMS;   // 4096 rows * 2 partitions = 8192
    splittopk_kernel<<<nblocks, THREADS, 65536>>>(x, out);
}

// round 2
// speedup vs baseline: 1.6005x; 1.6005x over previous
#include <cuda_runtime.h>
#include <cstdint>

#define THREADS 512
#define ELEMS   16384
#define VEC_ITER (ELEMS / 4 / THREADS)   // 8 float4 per thread
#define KSEL    32
#define CAP     4096
#define THRESH  1.75f

// Order-preserving float -> uint32 key (ascending float <-> ascending unsigned)
__device__ __forceinline__ unsigned f2key(float f) {
    unsigned u = __float_as_uint(f);
    return (u & 0x80000000u) ? ~u : (u | 0x80000000u);
}
// relu(value) recovered from key: keys with MSB=0 are negative floats -> 0
__device__ __forceinline__ float key2relu(unsigned k) {
    return (k & 0x80000000u) ? __uint_as_float(k ^ 0x80000000u) : 0.0f;
}

__global__ __launch_bounds__(THREADS)
void splittopk_kernel(const float* __restrict__ x, float* __restrict__ out)
{
    __shared__ unsigned       ckeys[CAP];   // 16 KB
    __shared__ unsigned short cidx[CAP];    //  8 KB
    __shared__ unsigned hist[256];
    __shared__ int s_cnt;
    __shared__ unsigned s_prefix;
    __shared__ int s_k;
    __shared__ int s_eqcnt;
    __shared__ int eq_idx[64];

    const int tid  = threadIdx.x;
    const int lane = tid & 31;
    const long long base = (long long)blockIdx.x * ELEMS;
    const float4* __restrict__ x4 = (const float4*)(x + base);
    float4* __restrict__ o4 = (float4*)(out + base);

    if (tid == 0) { s_cnt = 0; s_prefix = 0u; s_k = KSEL; s_eqcnt = 0; }
    __syncthreads();

    // ---- One streaming pass: load, zero output, compact candidates ----
    #pragma unroll
    for (int j = 0; j < VEC_ITER; ++j) {
        int p = j * THREADS + tid;
        float4 v = x4[p];
        o4[p] = make_float4(0.f, 0.f, 0.f, 0.f);
        float vv[4] = {v.x, v.y, v.z, v.w};
        #pragma unroll
        for (int c = 0; c < 4; ++c) {
            bool pred = vv[c] > THRESH;
            unsigned act = __ballot_sync(0xFFFFFFFFu, pred);
            if (pred) {
                int leader = __ffs(act) - 1;
                int wb;
                if (lane == leader) wb = atomicAdd(&s_cnt, __popc(act));
                wb = __shfl_sync(act, wb, leader);
                int pos = wb + __popc(act & ((1u << lane) - 1u));
                if (pos < CAP) {
                    ckeys[pos] = f2key(vv[c]);
                    cidx[pos]  = (unsigned short)(p * 4 + c);
                }
            }
        }
    }
    __syncthreads();

    const int cnt = s_cnt;

    if (cnt >= KSEL && cnt <= CAP) {
        // ======== FAST PATH: exact radix-select over ~hundreds of candidates ====
        #pragma unroll
        for (int pass = 0; pass < 4; ++pass) {
            const int shift = 24 - pass * 8;
            if (tid < 256) hist[tid] = 0u;
            __syncthreads();
            const unsigned pmask = (pass == 0) ? 0u : (0xFFFFFFFFu << (shift + 8));
            const unsigned pfx = s_prefix;
            for (int i = tid; i < cnt; i += THREADS) {
                unsigned k = ckeys[i];
                if ((k & pmask) == pfx)
                    atomicAdd(&hist[(k >> shift) & 255u], 1u);
            }
            __syncthreads();
            if (tid == 0) {
                int acc = 0; int b = 255;
                for (; b > 0; --b) {
                    int h = (int)hist[b];
                    if (acc + h >= s_k) break;
                    acc += h;
                }
                s_prefix = pfx | ((unsigned)b << shift);
                s_k -= acc;
            }
            __syncthreads();
        }
        const unsigned T = s_prefix;
        const int kneed  = s_k;
        const float vT   = key2relu(T);

        for (int i = tid; i < cnt; i += THREADS) {
            unsigned k = ckeys[i];
            if (k > T) {
                out[base + cidx[i]] = key2relu(k);
            } else if (k == T) {
                int pq = atomicAdd(&s_eqcnt, 1);
                if (pq < 64) eq_idx[pq] = cidx[i];
            }
        }
        __syncthreads();

        const int eqc = s_eqcnt;
        if (eqc == kneed) {
            if (tid < eqc) out[base + eq_idx[tid]] = vT;   // kneed <= 32 <= 64
        } else {
            // fp32 tie at threshold: keep kneed smallest original indices
            for (int i = tid; i < cnt; i += THREADS) {
                if (ckeys[i] == T) {
                    int my = cidx[i];
                    int rank = 0;
                    for (int j = 0; j < cnt; ++j)
                        rank += (ckeys[j] == T && cidx[j] < my);
                    if (rank < kneed) out[base + my] = vT;
                }
            }
        }
    } else {
        // ======== COLD PATH: exact full radix-select reading from global ========
        // (fires only when <32 values exceed THRESH or buffer overflow; always correct)
        #pragma unroll
        for (int pass = 0; pass < 4; ++pass) {
            const int shift = 24 - pass * 8;
            if (tid < 256) hist[tid] = 0u;
            __syncthreads();
            const unsigned pmask = (pass == 0) ? 0u : (0xFFFFFFFFu << (shift + 8));
            const unsigned pfx = s_prefix;
            for (int i = tid; i < ELEMS; i += THREADS) {
                unsigned k = f2key(x[base + i]);
                if ((k & pmask) == pfx)
                    atomicAdd(&hist[(k >> shift) & 255u], 1u);
            }
            __syncthreads();
            if (tid == 0) {
                int acc = 0; int b = 255;
                for (; b > 0; --b) {
                    int h = (int)hist[b];
                    if (acc + h >= s_k) break;
                    acc += h;
                }
                s_prefix = pfx | ((unsigned)b << shift);
                s_k -= acc;
            }
            __syncthreads();
        }
        const unsigned T = s_prefix;
        const int kneed  = s_k;
        const float vT   = key2relu(T);

        for (int i = tid; i < ELEMS; i += THREADS) {
            unsigned k = f2key(x[base + i]);
            if (k > T) {
                out[base + i] = key2relu(k);
            } else if (k == T) {
                int pq = atomicAdd(&s_eqcnt, 1);
                if (pq < 64) eq_idx[pq] = i;
            }
        }
        __syncthreads();

        const int eqc = s_eqcnt;
        if (eqc == kneed) {
            if (tid < eqc) out[base + eq_idx[tid]] = vT;
        } else {
            for (int i = tid; i < ELEMS; i += THREADS) {
                if (f2key(x[base + i]) == T) {
                    int rank = 0;
                    for (int j = 0; j < i; ++j) rank += (f2key(x[base + j]) == T);
                    if (rank < kneed) out[base + i] = vT;
                }
            }
        }
    }
}

extern "C" void kernel_launch(void* const* d_in, const int* in_sizes, int n_in,
                              void* d_out, int out_size) {
    const float* x = (const float*)d_in[0];
    float* out = (float*)d_out;
    int nblocks = out_size / ELEMS;   // 4096 rows * 2 partitions = 8192
    splittopk_kernel<<<nblocks, THREADS>>>(x, out);
}